// round 5
// baseline (speedup 1.0000x reference)
#include <cuda_runtime.h>
#include <cuda_fp16.h>
#include <cstdint>

#define DINLINE __device__ __forceinline__

// ---------------- problem constants ----------------
constexpr int BQ  = 8192;   // batch rows
constexpr int HID = 1024;   // hidden
constexpr int N9  = 9216;   // packed N: 7 sum gates + x3 + m3
constexpr int K16 = 2048;   // fp16 K: [xh | mh]
constexpr int K8  = 4096;   // int8 K: [xl8 | xh8 | ml8 | mh8]
// all packed row strides are 4096 bytes (K16*2 == K8*1)

// GEMM tiling: every stage is [128 rows x 128 bytes] per operand
constexpr int BM = 128, BN = 128, NSTAGE = 3;
constexpr int A_STAGE_BYTES = BM * 128;                      // 16384
constexpr int STAGE_BYTES   = 2 * A_STAGE_BYTES;             // 32768
constexpr int SMEM_DYN      = NSTAGE * STAGE_BYTES + 1024;

constexpr int MT = BQ / BM;   // 64
constexpr int NT = N9 / BN;   // 72
constexpr int GM = 8;         // m-supertile height

// combined int8 scale: s_hi * s_lo = 2^-4 * 2^-15 = 2^-19
constexpr float S_COMB = 1.0f / 524288.0f;

// ---------------- device scratch (static globals: allowed) ----------------
__device__ __half  g_A16[(size_t)BQ * K16];   // 32 MB
__device__ int8_t  g_A8 [(size_t)BQ * K8];    // 32 MB
__device__ __half  g_B16[(size_t)N9 * K16];   // 36 MB
__device__ int8_t  g_B8 [(size_t)N9 * K8];    // 36 MB
__device__ float   g_C  [(size_t)BQ * N9];    // 288 MB

// ---------------- PTX helpers (sm_80-class only) ----------------
DINLINE uint32_t smem_u32(const void* p) {
    uint32_t a;
    asm("{ .reg .u64 t; cvta.to.shared.u64 t, %1; cvt.u32.u64 %0, t; }"
        : "=r"(a) : "l"(p));
    return a;
}

DINLINE void cp16(uint32_t dst, const void* src) {
    asm volatile("cp.async.cg.shared.global [%0], [%1], 16;" :: "r"(dst), "l"(src));
}
DINLINE void cp_commit() { asm volatile("cp.async.commit_group;" ::: "memory"); }
DINLINE void cp_wait1()  { asm volatile("cp.async.wait_group 1;" ::: "memory"); }

DINLINE void ldsm4(uint32_t& r0, uint32_t& r1, uint32_t& r2, uint32_t& r3,
                   uint32_t addr) {
    asm volatile("ldmatrix.sync.aligned.m8n8.x4.shared.b16 {%0,%1,%2,%3}, [%4];"
                 : "=r"(r0), "=r"(r1), "=r"(r2), "=r"(r3) : "r"(addr));
}

// int8 MMA: s32 accumulator lives directly in uint32 storage
DINLINE void mma_i8(uint32_t* c, const uint32_t* a, const uint32_t* b) {
    asm volatile(
        "mma.sync.aligned.m16n8k32.row.col.s32.s8.s8.s32 "
        "{%0,%1,%2,%3}, {%4,%5,%6,%7}, {%8,%9}, {%0,%1,%2,%3};"
        : "+r"(c[0]), "+r"(c[1]), "+r"(c[2]), "+r"(c[3])
        : "r"(a[0]), "r"(a[1]), "r"(a[2]), "r"(a[3]), "r"(b[0]), "r"(b[1]));
}

// fp16 MMA on the same uint32 storage (mov.b32 bridges PTX reg classes;
// ptxas copy-propagates them away)
DINLINE void mma_f16(uint32_t* c, const uint32_t* a, const uint32_t* b) {
    asm volatile(
        "{\n\t.reg .f32 p0,p1,p2,p3;\n\t"
        "mov.b32 p0,%0; mov.b32 p1,%1; mov.b32 p2,%2; mov.b32 p3,%3;\n\t"
        "mma.sync.aligned.m16n8k16.row.col.f32.f16.f16.f32 "
        "{p0,p1,p2,p3}, {%4,%5,%6,%7}, {%8,%9}, {p0,p1,p2,p3};\n\t"
        "mov.b32 %0,p0; mov.b32 %1,p1; mov.b32 %2,p2; mov.b32 %3,p3;\n\t}"
        : "+r"(c[0]), "+r"(c[1]), "+r"(c[2]), "+r"(c[3])
        : "r"(a[0]), "r"(a[1]), "r"(a[2]), "r"(a[3]), "r"(b[0]), "r"(b[1]));
}

DINLINE int8_t q8(float v) {
    int t = __float2int_rn(v);
    t = t < -127 ? -127 : (t > 127 ? 127 : t);
    return (int8_t)t;
}

// ---------------- pack kernels ----------------
// A16 row b: [xh | mh] (1024 each). A8 row b: [xl8 | xh8 | ml8 | mh8].
__global__ void pack_A(const float* __restrict__ x, const float* __restrict__ m) {
    size_t idx = (size_t)blockIdx.x * blockDim.x + threadIdx.x;
    if (idx >= (size_t)BQ * 256) return;
    size_t b = idx >> 8;
    int k4 = (int)(idx & 255) * 4;

    float xs[4], ms[4];
    *(float4*)xs = *(const float4*)(x + b * 1024 + k4);
    *(float4*)ms = *(const float4*)(m + b * 1024 + k4);

    unsigned short xh[4], mh[4];
    int8_t xl8[4], xh8[4], ml8[4], mh8[4];
#pragma unroll
    for (int c = 0; c < 4; c++) {
        __half h = __float2half_rn(xs[c]);
        float hf = __half2float(h);
        xh[c] = __half_as_ushort(h);
        xh8[c] = q8(hf * 16.0f);
        xl8[c] = q8((xs[c] - hf) * 32768.0f);
        h = __float2half_rn(ms[c]);
        hf = __half2float(h);
        mh[c] = __half_as_ushort(h);
        mh8[c] = q8(hf * 16.0f);
        ml8[c] = q8((ms[c] - hf) * 32768.0f);
    }
    *(uint2*)&g_A16[b * K16 + k4]        = *(uint2*)xh;
    *(uint2*)&g_A16[b * K16 + 1024 + k4] = *(uint2*)mh;
    *(uint32_t*)&g_A8[b * K8 + k4]         = *(uint32_t*)xl8;
    *(uint32_t*)&g_A8[b * K8 + 1024 + k4]  = *(uint32_t*)xh8;
    *(uint32_t*)&g_A8[b * K8 + 2048 + k4]  = *(uint32_t*)ml8;
    *(uint32_t*)&g_A8[b * K8 + 3072 + k4]  = *(uint32_t*)mh8;
}

// B16 row n: [wih | wmh]. B8 row n: [wih8 | wil8 | wmh8 | wml8].
// (pairing: xl8*wih8 + xh8*wil8 + ml8*wmh8 + mh8*wml8, shared scale 2^-19)
__global__ void pack_B(const float* __restrict__ wi, const float* __restrict__ wm) {
    __shared__ float t[32][33];
    int ct = blockIdx.x;             // col tile over 8192
    int kt = blockIdx.y;             // k tile over 1024
    int z  = blockIdx.z;             // 0 = w_inputs, 1 = w_m
    const float* w = z ? wm : wi;
    int col0 = ct * 32, k0 = kt * 32;
    int tx = threadIdx.x, ty = threadIdx.y;
    for (int r = ty; r < 32; r += 8)
        t[r][tx] = w[(size_t)(k0 + r) * 8192 + col0 + tx];
    __syncthreads();
    for (int r = ty; r < 32; r += 8) {
        int col = col0 + r;
        int kk  = k0 + tx;
        float v = t[tx][r];          // = w[kk][col]
        __half h = __float2half_rn(v);
        float hf = __half2float(h);
        int8_t h8 = q8(hf * 16.0f);
        int8_t l8 = q8((v - hf) * 32768.0f);
        int g = col >> 10, hcol = col & 1023;
        size_t n;
        if (g == 3) n = z ? (size_t)(8192 + hcol) : (size_t)(7168 + hcol);
        else        n = (size_t)((g < 3 ? g : g - 1) * 1024 + hcol);
        g_B16[n * K16 + z * 1024 + kk] = h;
        g_B8[n * K8 + z * 2048 + kk]        = h8;
        g_B8[n * K8 + z * 2048 + 1024 + kk] = l8;
    }
}

// ---------------- GEMM: int8 correction phase + fp16 hi phase -------------
__global__ __launch_bounds__(128, 2)
void gemm_kernel() {
    extern __shared__ char dsmem[];
    char* tilep = (char*)(((uintptr_t)dsmem + 1023) & ~(uintptr_t)1023);
    uint32_t tile_base = smem_u32(tilep);

    int tid = threadIdx.x;
    int wid = tid >> 5;
    int lid = tid & 31;
    int wmo = (wid & 1) * 64;    // warp m-offset
    int wno = (wid >> 1) * 64;   // warp n-offset

    int bid = blockIdx.x;
    int mt = (bid / (GM * NT)) * GM + (bid % GM);
    int nt = (bid / GM) % NT;
    int m0 = mt * BM;
    int n0 = nt * BN;

    // region: shared byte offset + phase lengths (128B per stage)
    int koff, nk8, nk16;
    if (n0 >= 8192)      { koff = 2048; nk8 = 16; nk16 = 16; }   // m3
    else if (n0 >= 7168) { koff = 0;    nk8 = 16; nk16 = 16; }   // x3
    else                 { koff = 0;    nk8 = 32; nk16 = 32; }   // sum gates
    int NS = nk8 + nk16;

    const char* pA8  = (const char*)g_A8  + (size_t)m0 * 4096 + koff;
    const char* pA16 = (const char*)g_A16 + (size_t)m0 * 4096 + koff;
    const char* pB8  = (const char*)g_B8  + (size_t)n0 * 4096 + koff;
    const char* pB16 = (const char*)g_B16 + (size_t)n0 * 4096 + koff;

    auto fill_stage = [&](int s, int i) {
        const char* gA = (i < nk8) ? pA8 + i * 128 : pA16 + (i - nk8) * 128;
        const char* gB = (i < nk8) ? pB8 + i * 128 : pB16 + (i - nk8) * 128;
        uint32_t baseA = tile_base + s * STAGE_BYTES;
        uint32_t baseB = baseA + A_STAGE_BYTES;
#pragma unroll
        for (int j = 0; j < 16; j++) {
            int ch = tid + (j << 7);           // 0..2047
            int rr = (ch >> 3) & 127;
            int cc = ch & 7;
            uint32_t off = (uint32_t)((rr << 7) + (cc << 4));
            uint32_t sw  = off ^ ((off >> 3) & 0x70);
            const char* src = ((ch < 1024) ? gA : gB) + (size_t)rr * 4096 + (cc << 4);
            cp16(((ch < 1024) ? baseA : baseB) + sw, src);
        }
    };

    uint32_t acc[4][8][4];   // s32 during int8 phase, f32 bits afterwards
#pragma unroll
    for (int mf = 0; mf < 4; mf++)
#pragma unroll
        for (int nf = 0; nf < 8; nf++)
#pragma unroll
            for (int q = 0; q < 4; q++) acc[mf][nf][q] = 0u;

    fill_stage(0, 0); cp_commit();
    fill_stage(1, 1); cp_commit();

    int rowA = wmo + (lid & 15);                      // + mf*16
    int kAby = (lid >> 4) * 16;                       // + ks*32 bytes
    int rowB = wno + (lid & 7) + (lid >> 4) * 8;      // + nf2*16
    int kBby = ((lid >> 3) & 1) * 16;                 // + ks*32 bytes

    uint32_t aF[2][4][4];
    uint32_t bF[2][8][2];

    auto load_frags = [&](int buf, uint32_t sA, uint32_t sB, int ks) {
#pragma unroll
        for (int mf = 0; mf < 4; mf++) {
            uint32_t off = (uint32_t)((rowA + mf * 16) << 7);
            uint32_t addr = sA + off + (((uint32_t)(kAby + ks * 32)) ^ ((off >> 3) & 0x70));
            ldsm4(aF[buf][mf][0], aF[buf][mf][1], aF[buf][mf][2], aF[buf][mf][3], addr);
        }
#pragma unroll
        for (int nf2 = 0; nf2 < 4; nf2++) {
            uint32_t off = (uint32_t)((rowB + nf2 * 16) << 7);
            uint32_t addr = sB + off + (((uint32_t)(kBby + ks * 32)) ^ ((off >> 3) & 0x70));
            uint32_t r0, r1, r2, r3;
            ldsm4(r0, r1, r2, r3, addr);
            bF[buf][nf2 * 2][0] = r0;      bF[buf][nf2 * 2][1] = r1;
            bF[buf][nf2 * 2 + 1][0] = r2;  bF[buf][nf2 * 2 + 1][1] = r3;
        }
    };

    for (int i = 0; i < NS; i++) {
        int s = i - (i / NSTAGE) * NSTAGE;
        cp_wait1();                // fill(i) complete; fill(i+1) may fly
        __syncthreads();           // everyone done reading stage (i+2)%3
        if (i + 2 < NS) fill_stage((s + 2 >= NSTAGE) ? s + 2 - NSTAGE : s + 2, i + 2);
        cp_commit();               // unconditional: keeps group count per iter

        if (i == nk8) {            // int8 phase done -> convert acc to float
#pragma unroll
            for (int mf = 0; mf < 4; mf++)
#pragma unroll
                for (int nf = 0; nf < 8; nf++)
#pragma unroll
                    for (int q = 0; q < 4; q++)
                        acc[mf][nf][q] =
                            __float_as_uint((float)(int)acc[mf][nf][q] * S_COMB);
        }

        uint32_t sA = tile_base + s * STAGE_BYTES;
        uint32_t sB = sA + A_STAGE_BYTES;
        load_frags(0, sA, sB, 0);
        if (i < nk8) {
#pragma unroll
            for (int ks = 0; ks < 4; ks++) {
                int cur = ks & 1;
                if (ks < 3) load_frags(cur ^ 1, sA, sB, ks + 1);
#pragma unroll
                for (int mf = 0; mf < 4; mf++)
#pragma unroll
                    for (int nf = 0; nf < 8; nf++)
                        mma_i8(acc[mf][nf], aF[cur][mf], bF[cur][nf]);
            }
        } else {
#pragma unroll
            for (int ks = 0; ks < 4; ks++) {
                int cur = ks & 1;
                if (ks < 3) load_frags(cur ^ 1, sA, sB, ks + 1);
#pragma unroll
                for (int mf = 0; mf < 4; mf++)
#pragma unroll
                    for (int nf = 0; nf < 8; nf++)
                        mma_f16(acc[mf][nf], aF[cur][mf], bF[cur][nf]);
            }
        }
    }

    // epilogue: float2 stores
    int rr = lid >> 2;
    int cc2 = (lid & 3) * 2;
#pragma unroll
    for (int mf = 0; mf < 4; mf++) {
#pragma unroll
        for (int nf = 0; nf < 8; nf++) {
            int m = m0 + wmo + mf * 16 + rr;
            int n = n0 + wno + nf * 8 + cc2;
            float2 v0 = make_float2(__uint_as_float(acc[mf][nf][0]),
                                    __uint_as_float(acc[mf][nf][1]));
            float2 v1 = make_float2(__uint_as_float(acc[mf][nf][2]),
                                    __uint_as_float(acc[mf][nf][3]));
            *(float2*)&g_C[(size_t)m * N9 + n] = v0;
            *(float2*)&g_C[(size_t)(m + 8) * N9 + n] = v1;
        }
    }
}

// ---------------- combine: gate network (float2-vectorized) ----------------
DINLINE float sigf(float v) { return 1.0f / (1.0f + expf(-v)); }

DINLINE float gate_net(float s0, float s1, float s2, float s4, float s5,
                       float s6, float s7, float x3, float m3,
                       float cp, float& nc) {
    float l10 = sigf(s0);
    float l11 = fmaxf(s1, 0.0f);
    float l12 = sigf(s2);
    float l13 = fmaxf(x3 * m3, 0.0f);
    float l14 = tanhf(s4);
    float l15 = sigf(s5);
    float l16 = tanhf(s6);
    float l17 = sigf(s7);
    float l20 = tanhf(l10 * l11);
    float l21 = tanhf(l12 + l13);
    float l22 = tanhf(l14 * l15);
    float l23 = sigf(l16 + l17);
    l20 = tanhf(l20 + cp);
    nc = l20 * l21;
    float l31 = tanhf(l22 + l23);
    return tanhf(nc * l31);
}

__global__ void combine_kernel(const float* __restrict__ c_prev, float* __restrict__ out) {
    size_t idx = (size_t)blockIdx.x * blockDim.x + threadIdx.x;
    if (idx >= (size_t)BQ * (HID / 2)) return;
    size_t b  = idx >> 9;
    int    h2 = (int)(idx & 511);
    const float2* Cr = (const float2*)(g_C + b * N9) + h2;
    float2 s0 = Cr[0],        s1 = Cr[512],      s2 = Cr[1024];
    float2 s4 = Cr[1536],     s5 = Cr[2048],     s6 = Cr[2560];
    float2 s7 = Cr[3072],     x3 = Cr[3584],     m3 = Cr[4096];
    float2 cp = *((const float2*)c_prev + b * 512 + h2);

    float2 nm, nc;
    nm.x = gate_net(s0.x, s1.x, s2.x, s4.x, s5.x, s6.x, s7.x, x3.x, m3.x, cp.x, nc.x);
    nm.y = gate_net(s0.y, s1.y, s2.y, s4.y, s5.y, s6.y, s7.y, x3.y, m3.y, cp.y, nc.y);

    float2* o = (float2*)out;
    o[b * 512 + h2] = nm;                                  // new_m
    o[(size_t)BQ * 512 + b * 512 + h2] = nc;               // new_c
}

// ---------------- launch ----------------
extern "C" void kernel_launch(void* const* d_in, const int* in_sizes, int n_in,
                              void* d_out, int out_size) {
    const float* x      = (const float*)d_in[0];
    const float* m_prev = (const float*)d_in[1];
    const float* c_prev = (const float*)d_in[2];
    const float* w_m    = (const float*)d_in[3];
    const float* w_in   = (const float*)d_in[4];
    float* out = (float*)d_out;

    cudaFuncSetAttribute(gemm_kernel, cudaFuncAttributeMaxDynamicSharedMemorySize, SMEM_DYN);

    {   // pack A (fp16 hi + int8 residual digits), 4 elems/thread
        size_t n = (size_t)BQ * 256;
        pack_A<<<(unsigned)((n + 255) / 256), 256>>>(x, m_prev);
    }
    {   // pack B (transpose + fp16 hi + int8 digits)
        dim3 grid(256, 32, 2), blk(32, 8);
        pack_B<<<grid, blk>>>(w_in, w_m);
    }
    {   // the single big two-phase GEMM
        gemm_kernel<<<MT * NT, 128, SMEM_DYN>>>();
    }
    {   // gate network
        size_t n = (size_t)BQ * (HID / 2);
        combine_kernel<<<(unsigned)((n + 255) / 256), 256>>>(c_prev, out);
    }
    (void)in_sizes; (void)n_in; (void)out_size;
}

// round 6
// speedup vs baseline: 2.1484x; 2.1484x over previous
#include <cuda_runtime.h>
#include <cuda_bf16.h>
#include <cstdint>

#define DINLINE __device__ __forceinline__

// ---------------- problem constants ----------------
constexpr int BQ  = 8192;   // batch rows
constexpr int HID = 1024;   // hidden
constexpr int K6  = 6144;   // packed K (6 blocks of 1024)
constexpr int N9  = 9216;   // packed N (7 sum gates + x3 + m3)

// GEMM tiling: 128x256 CTA tile, BK=64, 4-stage pipeline, 8 warps
constexpr int BM = 128, BN = 256, BK = 64, NSTAGE = 4;
constexpr int A_STAGE_BYTES = BM * BK * 2;                   // 16384
constexpr int B_STAGE_BYTES = BN * BK * 2;                   // 32768
constexpr int STAGE_BYTES   = A_STAGE_BYTES + B_STAGE_BYTES; // 49152
constexpr int SMEM_DYN      = NSTAGE * STAGE_BYTES + 1024;   // ~193 KB

constexpr int MT = BQ / BM;   // 64 m-tiles
constexpr int NT = N9 / BN;   // 36 n-tiles
constexpr int GM = 8;         // m-supertile height

// ---------------- device scratch (static globals: allowed) ----------------
__device__ __nv_bfloat16 g_A[(size_t)BQ * K6];   // 96 MB
__device__ __nv_bfloat16 g_B[(size_t)N9 * K6];   // 108 MB
__device__ float         g_C[(size_t)BQ * N9];   // 288 MB

// ---------------- PTX helpers (sm_80-class only) ----------------
DINLINE uint32_t smem_u32(const void* p) {
    uint32_t a;
    asm("{ .reg .u64 t; cvta.to.shared.u64 t, %1; cvt.u32.u64 %0, t; }"
        : "=r"(a) : "l"(p));
    return a;
}

DINLINE void cp16(uint32_t dst, const void* src) {
    asm volatile("cp.async.cg.shared.global [%0], [%1], 16;" :: "r"(dst), "l"(src));
}
DINLINE void cp_commit() { asm volatile("cp.async.commit_group;" ::: "memory"); }
DINLINE void cp_wait2()  { asm volatile("cp.async.wait_group 2;" ::: "memory"); }

DINLINE void ldsm4(uint32_t& r0, uint32_t& r1, uint32_t& r2, uint32_t& r3,
                   uint32_t addr) {
    asm volatile("ldmatrix.sync.aligned.m8n8.x4.shared.b16 {%0,%1,%2,%3}, [%4];"
                 : "=r"(r0), "=r"(r1), "=r"(r2), "=r"(r3) : "r"(addr));
}

DINLINE void mma16816(float* c, const uint32_t* a, const uint32_t* b) {
    asm volatile(
        "mma.sync.aligned.m16n8k16.row.col.f32.bf16.bf16.f32 "
        "{%0,%1,%2,%3}, {%4,%5,%6,%7}, {%8,%9}, {%0,%1,%2,%3};"
        : "+f"(c[0]), "+f"(c[1]), "+f"(c[2]), "+f"(c[3])
        : "r"(a[0]), "r"(a[1]), "r"(a[2]), "r"(a[3]), "r"(b[0]), "r"(b[1]));
}

// ---------------- pack kernels ----------------
// A'' row b: [x_hi | x_lo | x_hi | m_hi | m_lo | m_hi], each block 1024 wide
__global__ void pack_A(const float* __restrict__ x, const float* __restrict__ m) {
    size_t i = (size_t)blockIdx.x * blockDim.x + threadIdx.x;
    if (i >= (size_t)BQ * HID) return;
    size_t b = i >> 10;
    int kk = (int)(i & 1023);
    float xv = x[i];
    __nv_bfloat16 xh = __float2bfloat16(xv);
    __nv_bfloat16 xl = __float2bfloat16(xv - __bfloat162float(xh));
    float mv = m[i];
    __nv_bfloat16 mh = __float2bfloat16(mv);
    __nv_bfloat16 ml = __float2bfloat16(mv - __bfloat162float(mh));
    size_t row = b * K6;
    g_A[row +        kk] = xh;
    g_A[row + 1024 + kk] = xl;
    g_A[row + 2048 + kk] = xh;
    g_A[row + 3072 + kk] = mh;
    g_A[row + 4096 + kk] = ml;
    g_A[row + 5120 + kk] = mh;
}

// B'' [N9, K6] K-major (transposed weights). blockIdx.z: 0 = w_inputs, 1 = w_m
__global__ void pack_B(const float* __restrict__ wi, const float* __restrict__ wm) {
    __shared__ float t[32][33];
    int ct = blockIdx.x;             // col tile over 8192 (256 tiles)
    int kt = blockIdx.y;             // k tile over 1024 (32 tiles)
    const float* w = blockIdx.z ? wm : wi;
    int col0 = ct * 32, k0 = kt * 32;
    int tx = threadIdx.x, ty = threadIdx.y;
    for (int r = ty; r < 32; r += 8)
        t[r][tx] = w[(size_t)(k0 + r) * 8192 + col0 + tx];
    __syncthreads();
    for (int r = ty; r < 32; r += 8) {
        int col = col0 + r;
        int kk  = k0 + tx;
        float v = t[tx][r];          // = w[kk][col]
        __nv_bfloat16 hi = __float2bfloat16(v);
        __nv_bfloat16 lo = __float2bfloat16(v - __bfloat162float(hi));
        int g = col >> 10, h = col & 1023;
        size_t n;
        int kb0, kb1, kb2;
        if (blockIdx.z == 0) {       // w_inputs -> K-blocks 0,1 = hi; 2 = lo
            n = (g == 3) ? (size_t)(7168 + h) : (size_t)((g < 3 ? g : g - 1) * 1024 + h);
            kb0 = 0; kb1 = 1024; kb2 = 2048;
        } else {                     // w_m -> K-blocks 3,4 = hi; 5 = lo
            n = (g == 3) ? (size_t)(8192 + h) : (size_t)((g < 3 ? g : g - 1) * 1024 + h);
            kb0 = 3072; kb1 = 4096; kb2 = 5120;
        }
        size_t base = n * K6;
        g_B[base + kb0 + kk] = hi;
        g_B[base + kb1 + kk] = hi;
        g_B[base + kb2 + kk] = lo;
    }
}

// ---------------- GEMM: C[8192, 9216] = A''[8192,6144] @ B''^T ----------------
// 128x256 CTA tile, 8 warps (2m x 4n of 64x64), 4-stage pipeline
__global__ __launch_bounds__(256, 1)
void gemm_kernel() {
    extern __shared__ char dsmem[];
    char* tilep = (char*)(((uintptr_t)dsmem + 1023) & ~(uintptr_t)1023);
    uint32_t tile_base = smem_u32(tilep);

    int tid = threadIdx.x;
    int wid = tid >> 5;
    int lid = tid & 31;
    int wmo = (wid & 1) * 64;    // warp m-offset (2 warps in m)
    int wno = (wid >> 1) * 64;   // warp n-offset (4 warps in n)

    // supertile rasterization: bands of GM m-tiles sweep all n for L2 reuse
    int bid = blockIdx.x;
    int mt = (bid / (GM * NT)) * GM + (bid % GM);
    int nt = (bid / GM) % NT;
    int m0 = mt * BM;
    int n0 = nt * BN;

    int kbeg = 0, kend = K6;
    if (n0 >= 8192)       kbeg = 3072;   // m3 region: only m K-blocks
    else if (n0 >= 7168)  kend = 3072;   // x3 region: only x K-blocks
    int NK = (kend - kbeg) >> 6;

    const char* gAbase = (const char*)g_A + (size_t)m0 * (K6 * 2);
    const char* gBbase = (const char*)g_B + (size_t)n0 * (K6 * 2);

    auto fill_stage = [&](int s, int k0) {
        uint32_t baseA = tile_base + s * STAGE_BYTES;
        uint32_t baseB = baseA + A_STAGE_BYTES;
        const char* gA = gAbase + (size_t)k0 * 2;
        const char* gB = gBbase + (size_t)k0 * 2;
#pragma unroll
        for (int j = 0; j < 12; j++) {
            int ch = tid + (j << 8);           // 0..3071
            if (ch < 1024) {
                int rr = ch >> 3, cc = ch & 7;
                uint32_t off = (uint32_t)((rr << 7) + (cc << 4));
                uint32_t sw  = off ^ ((off >> 3) & 0x70);
                cp16(baseA + sw, gA + (size_t)rr * (K6 * 2) + (cc << 4));
            } else {
                int c2 = ch - 1024;
                int rr = c2 >> 3, cc = c2 & 7;  // rr 0..255
                uint32_t off = (uint32_t)((rr << 7) + (cc << 4));
                uint32_t sw  = off ^ ((off >> 3) & 0x70);
                cp16(baseB + sw, gB + (size_t)rr * (K6 * 2) + (cc << 4));
            }
        }
    };

    float acc[4][8][4];
#pragma unroll
    for (int mf = 0; mf < 4; mf++)
#pragma unroll
        for (int nf = 0; nf < 8; nf++)
#pragma unroll
            for (int q = 0; q < 4; q++) acc[mf][nf][q] = 0.0f;

    // prologue: 3 stages in flight
    fill_stage(0, kbeg);           cp_commit();
    fill_stage(1, kbeg + BK);      cp_commit();
    fill_stage(2, kbeg + 2 * BK);  cp_commit();

    int rowA = wmo + (lid & 15);                      // + mf*16
    int kAby = ((lid >> 4) * 8) * 2;                  // + ks*32 bytes
    int rowB = wno + (lid & 7) + (lid >> 4) * 8;      // + nf2*16
    int kBby = (((lid >> 3) & 1) * 8) * 2;            // + ks*32 bytes

    uint32_t aF[2][4][4];
    uint32_t bF[2][8][2];

    auto load_frags = [&](int buf, uint32_t sA, uint32_t sB, int ks) {
#pragma unroll
        for (int mf = 0; mf < 4; mf++) {
            uint32_t off = (uint32_t)((rowA + mf * 16) << 7);
            uint32_t addr = sA + off + (((uint32_t)(kAby + ks * 32)) ^ ((off >> 3) & 0x70));
            ldsm4(aF[buf][mf][0], aF[buf][mf][1], aF[buf][mf][2], aF[buf][mf][3], addr);
        }
#pragma unroll
        for (int nf2 = 0; nf2 < 4; nf2++) {
            uint32_t off = (uint32_t)((rowB + nf2 * 16) << 7);
            uint32_t addr = sB + off + (((uint32_t)(kBby + ks * 32)) ^ ((off >> 3) & 0x70));
            uint32_t r0, r1, r2, r3;
            ldsm4(r0, r1, r2, r3, addr);
            bF[buf][nf2 * 2][0] = r0;      bF[buf][nf2 * 2][1] = r1;
            bF[buf][nf2 * 2 + 1][0] = r2;  bF[buf][nf2 * 2 + 1][1] = r3;
        }
    };

    for (int i = 0; i < NK; i++) {
        int s = i & (NSTAGE - 1);
        cp_wait2();                // fill(i) complete (fills i+1,i+2 may fly)
        __syncthreads();           // all warps done reading stage (i+3)%4
        if (i + 3 < NK) fill_stage((i + 3) & (NSTAGE - 1), kbeg + (i + 3) * BK);
        cp_commit();               // unconditional: uniform group accounting

        uint32_t sA = tile_base + s * STAGE_BYTES;
        uint32_t sB = sA + A_STAGE_BYTES;
        load_frags(0, sA, sB, 0);
#pragma unroll
        for (int ks = 0; ks < 4; ks++) {
            int cur = ks & 1;
            if (ks < 3) load_frags(cur ^ 1, sA, sB, ks + 1);
#pragma unroll
            for (int mf = 0; mf < 4; mf++)
#pragma unroll
                for (int nf = 0; nf < 8; nf++)
                    mma16816(acc[mf][nf], aF[cur][mf], bF[cur][nf]);
        }
    }

    // epilogue: direct register -> gmem (float2 per frag-row)
    int rr = lid >> 2;
    int cc2 = (lid & 3) * 2;
#pragma unroll
    for (int mf = 0; mf < 4; mf++) {
#pragma unroll
        for (int nf = 0; nf < 8; nf++) {
            int m = m0 + wmo + mf * 16 + rr;
            int n = n0 + wno + nf * 8 + cc2;
            float2 v0 = make_float2(acc[mf][nf][0], acc[mf][nf][1]);
            float2 v1 = make_float2(acc[mf][nf][2], acc[mf][nf][3]);
            *(float2*)&g_C[(size_t)m * N9 + n] = v0;
            *(float2*)&g_C[(size_t)(m + 8) * N9 + n] = v1;
        }
    }
}

// ---------------- combine: gate network (float2-vectorized) ----------------
DINLINE float sigf(float v) { return 1.0f / (1.0f + expf(-v)); }

DINLINE float gate_net(float s0, float s1, float s2, float s4, float s5,
                       float s6, float s7, float x3, float m3,
                       float cp, float& nc) {
    float l10 = sigf(s0);
    float l11 = fmaxf(s1, 0.0f);
    float l12 = sigf(s2);
    float l13 = fmaxf(x3 * m3, 0.0f);
    float l14 = tanhf(s4);
    float l15 = sigf(s5);
    float l16 = tanhf(s6);
    float l17 = sigf(s7);
    float l20 = tanhf(l10 * l11);
    float l21 = tanhf(l12 + l13);
    float l22 = tanhf(l14 * l15);
    float l23 = sigf(l16 + l17);
    l20 = tanhf(l20 + cp);
    nc = l20 * l21;
    float l31 = tanhf(l22 + l23);
    return tanhf(nc * l31);
}

__global__ void combine_kernel(const float* __restrict__ c_prev, float* __restrict__ out) {
    size_t idx = (size_t)blockIdx.x * blockDim.x + threadIdx.x;
    if (idx >= (size_t)BQ * (HID / 2)) return;
    size_t b  = idx >> 9;
    int    h2 = (int)(idx & 511);
    const float2* Cr = (const float2*)(g_C + b * N9) + h2;
    float2 s0 = Cr[0],        s1 = Cr[512],      s2 = Cr[1024];
    float2 s4 = Cr[1536],     s5 = Cr[2048],     s6 = Cr[2560];
    float2 s7 = Cr[3072],     x3 = Cr[3584],     m3 = Cr[4096];
    float2 cp = *((const float2*)c_prev + b * 512 + h2);

    float2 nm, nc;
    nm.x = gate_net(s0.x, s1.x, s2.x, s4.x, s5.x, s6.x, s7.x, x3.x, m3.x, cp.x, nc.x);
    nm.y = gate_net(s0.y, s1.y, s2.y, s4.y, s5.y, s6.y, s7.y, x3.y, m3.y, cp.y, nc.y);

    float2* o = (float2*)out;
    o[b * 512 + h2] = nm;                                  // new_m
    o[(size_t)BQ * 512 + b * 512 + h2] = nc;               // new_c
}

// ---------------- launch ----------------
extern "C" void kernel_launch(void* const* d_in, const int* in_sizes, int n_in,
                              void* d_out, int out_size) {
    const float* x      = (const float*)d_in[0];
    const float* m_prev = (const float*)d_in[1];
    const float* c_prev = (const float*)d_in[2];
    const float* w_m    = (const float*)d_in[3];
    const float* w_in   = (const float*)d_in[4];
    float* out = (float*)d_out;

    cudaFuncSetAttribute(gemm_kernel, cudaFuncAttributeMaxDynamicSharedMemorySize, SMEM_DYN);

    {   // pack A''
        size_t n = (size_t)BQ * HID;
        pack_A<<<(unsigned)((n + 255) / 256), 256>>>(x, m_prev);
    }
    {   // pack B'' (transpose + bf16 hi/lo split)
        dim3 grid(256, 32, 2), blk(32, 8);
        pack_B<<<grid, blk>>>(w_in, w_m);
    }
    {   // the single big GEMM
        gemm_kernel<<<MT * NT, 256, SMEM_DYN>>>();
    }
    {   // gate network
        size_t n = (size_t)BQ * (HID / 2);
        combine_kernel<<<(unsigned)((n + 255) / 256), 256>>>(c_prev, out);
    }
    (void)in_sizes; (void)n_in; (void)out_size;
}

// round 9
// speedup vs baseline: 2.4509x; 1.1408x over previous
#include <cuda_runtime.h>
#include <cuda_fp16.h>
#include <cstdint>

#define DINLINE __device__ __forceinline__

// ---------------- problem constants ----------------
constexpr int BQ  = 8192;   // batch rows
constexpr int HID = 1024;   // hidden
constexpr int N9  = 9216;   // packed N: 7 sum gates + x3 + m3
constexpr int KC  = 4096;   // correction K (fp16-acc phase): [xl | xh | ml | mh]
constexpr int KM  = 2048;   // main K (f32-acc phase): [xh | mh]

// GEMM tiling: 128x128 CTA tile, 4 warps, 3 stages, 2 CTA/SM
constexpr int BM = 128, BN = 128, NSTAGE = 3;
constexpr int A_STAGE_BYTES = BM * 128;                      // 16384 (128B/row)
constexpr int STAGE_BYTES   = 2 * A_STAGE_BYTES;             // 32768
constexpr int SMEM_DYN      = NSTAGE * STAGE_BYTES + 1024;

constexpr int MT = BQ / BM;   // 64
constexpr int NT = N9 / BN;   // 72
constexpr int GM = 8;         // m-supertile height

// ---------------- device scratch (static globals: allowed) ----------------
__device__ __half g_Ac[(size_t)BQ * KC];   // 64 MB  corrections
__device__ __half g_Am[(size_t)BQ * KM];   // 32 MB  main
__device__ __half g_Bc[(size_t)N9 * KC];   // 72 MB
__device__ __half g_Bm[(size_t)N9 * KM];   // 36 MB
__device__ float  g_C [(size_t)BQ * N9];   // 288 MB

// ---------------- PTX helpers (sm_80-class only) ----------------
DINLINE uint32_t smem_u32(const void* p) {
    uint32_t a;
    asm("{ .reg .u64 t; cvta.to.shared.u64 t, %1; cvt.u32.u64 %0, t; }"
        : "=r"(a) : "l"(p));
    return a;
}

DINLINE void cp16(uint32_t dst, const void* src) {
    asm volatile("cp.async.cg.shared.global [%0], [%1], 16;" :: "r"(dst), "l"(src));
}
DINLINE void cp_commit() { asm volatile("cp.async.commit_group;" ::: "memory"); }
DINLINE void cp_wait1()  { asm volatile("cp.async.wait_group 1;" ::: "memory"); }

DINLINE void ldsm4(uint32_t& r0, uint32_t& r1, uint32_t& r2, uint32_t& r3,
                   uint32_t addr) {
    asm volatile("ldmatrix.sync.aligned.m8n8.x4.shared.b16 {%0,%1,%2,%3}, [%4];"
                 : "=r"(r0), "=r"(r1), "=r"(r2), "=r"(r3) : "r"(addr));
}

// fp16 x fp16 -> f32 accumulate, acc stored as uint32 bits (mov bridges
// register classes; ptxas copy-propagates them away — proven in R5)
DINLINE void mma_f32(uint32_t* c, const uint32_t* a, const uint32_t* b) {
    asm volatile(
        "{\n\t.reg .f32 p0,p1,p2,p3;\n\t"
        "mov.b32 p0,%0; mov.b32 p1,%1; mov.b32 p2,%2; mov.b32 p3,%3;\n\t"
        "mma.sync.aligned.m16n8k16.row.col.f32.f16.f16.f32 "
        "{p0,p1,p2,p3}, {%4,%5,%6,%7}, {%8,%9}, {p0,p1,p2,p3};\n\t"
        "mov.b32 %0,p0; mov.b32 %1,p1; mov.b32 %2,p2; mov.b32 %3,p3;\n\t}"
        : "+r"(c[0]), "+r"(c[1]), "+r"(c[2]), "+r"(c[3])
        : "r"(a[0]), "r"(a[1]), "r"(a[2]), "r"(a[3]), "r"(b[0]), "r"(b[1]));
}

// fp16 x fp16 -> f16 accumulate (2 packed regs)
DINLINE void mma_f16(uint32_t* c, const uint32_t* a, const uint32_t* b) {
    asm volatile(
        "mma.sync.aligned.m16n8k16.row.col.f16.f16.f16.f16 "
        "{%0,%1}, {%2,%3,%4,%5}, {%6,%7}, {%0,%1};"
        : "+r"(c[0]), "+r"(c[1])
        : "r"(a[0]), "r"(a[1]), "r"(a[2]), "r"(a[3]), "r"(b[0]), "r"(b[1]));
}

// reinterpret uint32 bits as __half2 (defined BEFORE use this time)
DINLINE __half2 u32_as_half2(uint32_t u) {
    __half2 h;
    *(uint32_t*)&h = u;
    return h;
}

// ---------------- pack kernels ----------------
// Am row b: [xh | mh]. Ac row b: [xl | xh | ml | mh]  (all fp16)
__global__ void pack_A(const float* __restrict__ x, const float* __restrict__ m) {
    size_t idx = (size_t)blockIdx.x * blockDim.x + threadIdx.x;
    if (idx >= (size_t)BQ * 256) return;
    size_t b = idx >> 8;
    int k4 = (int)(idx & 255) * 4;

    float xs[4], ms[4];
    *(float4*)xs = *(const float4*)(x + b * 1024 + k4);
    *(float4*)ms = *(const float4*)(m + b * 1024 + k4);

    unsigned short xh[4], xl[4], mh[4], ml[4];
#pragma unroll
    for (int c = 0; c < 4; c++) {
        __half h = __float2half_rn(xs[c]);
        xh[c] = __half_as_ushort(h);
        xl[c] = __half_as_ushort(__float2half_rn(xs[c] - __half2float(h)));
        h = __float2half_rn(ms[c]);
        mh[c] = __half_as_ushort(h);
        ml[c] = __half_as_ushort(__float2half_rn(ms[c] - __half2float(h)));
    }
    *(uint2*)&g_Am[b * KM + k4]        = *(uint2*)xh;
    *(uint2*)&g_Am[b * KM + 1024 + k4] = *(uint2*)mh;
    *(uint2*)&g_Ac[b * KC + k4]        = *(uint2*)xl;
    *(uint2*)&g_Ac[b * KC + 1024 + k4] = *(uint2*)xh;
    *(uint2*)&g_Ac[b * KC + 2048 + k4] = *(uint2*)ml;
    *(uint2*)&g_Ac[b * KC + 3072 + k4] = *(uint2*)mh;
}

// Bm row n: [wih | wmh]. Bc row n: [wih | wil | wmh | wml]
// (corr pairing: xl*wih + xh*wil + ml*wmh + mh*wml)
__global__ void pack_B(const float* __restrict__ wi, const float* __restrict__ wm) {
    __shared__ float t[32][33];
    int ct = blockIdx.x;             // col tile over 8192
    int kt = blockIdx.y;             // k tile over 1024
    int z  = blockIdx.z;             // 0 = w_inputs, 1 = w_m
    const float* w = z ? wm : wi;
    int col0 = ct * 32, k0 = kt * 32;
    int tx = threadIdx.x, ty = threadIdx.y;
    for (int r = ty; r < 32; r += 8)
        t[r][tx] = w[(size_t)(k0 + r) * 8192 + col0 + tx];
    __syncthreads();
    for (int r = ty; r < 32; r += 8) {
        int col = col0 + r;
        int kk  = k0 + tx;
        float v = t[tx][r];          // = w[kk][col]
        __half hi = __float2half_rn(v);
        __half lo = __float2half_rn(v - __half2float(hi));
        int g = col >> 10, h = col & 1023;
        size_t n;
        if (g == 3) n = z ? (size_t)(8192 + h) : (size_t)(7168 + h);
        else        n = (size_t)((g < 3 ? g : g - 1) * 1024 + h);
        g_Bm[n * KM + z * 1024 + kk] = hi;
        g_Bc[n * KC + z * 2048 + kk]        = hi;   // wih / wmh
        g_Bc[n * KC + z * 2048 + 1024 + kk] = lo;   // wil / wml
    }
}

// ---------------- GEMM: fp16-acc correction phase + f32-acc main phase ----
__global__ __launch_bounds__(128, 2)
void gemm_kernel() {
    extern __shared__ char dsmem[];
    char* tilep = (char*)(((uintptr_t)dsmem + 1023) & ~(uintptr_t)1023);
    uint32_t tile_base = smem_u32(tilep);

    int tid = threadIdx.x;
    int wid = tid >> 5;
    int lid = tid & 31;
    int wmo = (wid & 1) * 64;    // warp m-offset (2 warps in m)
    int wno = (wid >> 1) * 64;   // warp n-offset (2 warps in n)

    int bid = blockIdx.x;
    int mt = (bid / (GM * NT)) * GM + (bid % GM);
    int nt = (bid / GM) % NT;
    int m0 = mt * BM;
    int n0 = nt * BN;

    // region: byte offsets within packed rows + stage counts (128B each)
    int cbeg, nc, mbeg, nm;
    if (n0 >= 8192)      { cbeg = 4096; nc = 32; mbeg = 2048; nm = 16; } // m3
    else if (n0 >= 7168) { cbeg = 0;    nc = 32; mbeg = 0;    nm = 16; } // x3
    else                 { cbeg = 0;    nc = 64; mbeg = 0;    nm = 32; } // sums
    int NS = nc + nm;

    const char* pAc = (const char*)g_Ac + (size_t)m0 * (KC * 2) + cbeg;
    const char* pAm = (const char*)g_Am + (size_t)m0 * (KM * 2) + mbeg;
    const char* pBc = (const char*)g_Bc + (size_t)n0 * (KC * 2) + cbeg;
    const char* pBm = (const char*)g_Bm + (size_t)n0 * (KM * 2) + mbeg;

    auto fill_stage = [&](int s, int i) {
        bool corr = (i < nc);
        const char* gA = corr ? pAc + i * 128 : pAm + (i - nc) * 128;
        const char* gB = corr ? pBc + i * 128 : pBm + (i - nc) * 128;
        size_t stride = corr ? (size_t)(KC * 2) : (size_t)(KM * 2);
        uint32_t baseA = tile_base + s * STAGE_BYTES;
        uint32_t baseB = baseA + A_STAGE_BYTES;
#pragma unroll
        for (int j = 0; j < 16; j++) {
            int ch = tid + (j << 7);           // 0..2047
            int rr = (ch >> 3) & 127;
            int cc = ch & 7;
            uint32_t off = (uint32_t)((rr << 7) + (cc << 4));
            uint32_t sw  = off ^ ((off >> 3) & 0x70);
            const char* src = ((ch < 1024) ? gA : gB) + (size_t)rr * stride + (cc << 4);
            cp16(((ch < 1024) ? baseA : baseB) + sw, src);
        }
    };

    // single accumulator array: f16 pair in [0..1] during correction phase,
    // f32 bits in [0..3] after the in-place conversion (no simultaneous
    // double-size accumulator state -> no spills)
    uint32_t acc[4][8][4];
#pragma unroll
    for (int mf = 0; mf < 4; mf++)
#pragma unroll
        for (int nf = 0; nf < 8; nf++) {
            acc[mf][nf][0] = 0u; acc[mf][nf][1] = 0u;
            acc[mf][nf][2] = 0u; acc[mf][nf][3] = 0u;
        }

    fill_stage(0, 0); cp_commit();
    fill_stage(1, 1); cp_commit();

    int rowA = wmo + (lid & 15);                      // + mf*16
    int kAby = (lid >> 4) * 16;                       // + ks*32 bytes
    int rowB = wno + (lid & 7) + (lid >> 4) * 8;      // + nf2*16
    int kBby = ((lid >> 3) & 1) * 16;                 // + ks*32 bytes

    uint32_t aF[2][4][4];
    uint32_t bF[2][8][2];

    auto load_frags = [&](int buf, uint32_t sA, uint32_t sB, int ks) {
#pragma unroll
        for (int mf = 0; mf < 4; mf++) {
            uint32_t off = (uint32_t)((rowA + mf * 16) << 7);
            uint32_t addr = sA + off + (((uint32_t)(kAby + ks * 32)) ^ ((off >> 3) & 0x70));
            ldsm4(aF[buf][mf][0], aF[buf][mf][1], aF[buf][mf][2], aF[buf][mf][3], addr);
        }
#pragma unroll
        for (int nf2 = 0; nf2 < 4; nf2++) {
            uint32_t off = (uint32_t)((rowB + nf2 * 16) << 7);
            uint32_t addr = sB + off + (((uint32_t)(kBby + ks * 32)) ^ ((off >> 3) & 0x70));
            uint32_t r0, r1, r2, r3;
            ldsm4(r0, r1, r2, r3, addr);
            bF[buf][nf2 * 2][0] = r0;      bF[buf][nf2 * 2][1] = r1;
            bF[buf][nf2 * 2 + 1][0] = r2;  bF[buf][nf2 * 2 + 1][1] = r3;
        }
    };

    for (int i = 0; i < NS; i++) {
        int s = i - (i / NSTAGE) * NSTAGE;            // i % 3
        // SAFE pipeline order (R5-proven): wait for fill(i), barrier so all
        // warps are done reading stage (i+2)%3, only THEN overwrite it.
        cp_wait1();
        __syncthreads();
        if (i + 2 < NS) fill_stage((s + 2 >= NSTAGE) ? s + 2 - NSTAGE : s + 2, i + 2);
        cp_commit();

        if (i == nc) {   // phase boundary: expand fp16 acc -> f32 bits, in place
#pragma unroll
            for (int mf = 0; mf < 4; mf++)
#pragma unroll
                for (int nf = 0; nf < 8; nf++) {
                    float2 lo = __half22float2(u32_as_half2(acc[mf][nf][0]));
                    float2 hi = __half22float2(u32_as_half2(acc[mf][nf][1]));
                    acc[mf][nf][0] = __float_as_uint(lo.x);
                    acc[mf][nf][1] = __float_as_uint(lo.y);
                    acc[mf][nf][2] = __float_as_uint(hi.x);
                    acc[mf][nf][3] = __float_as_uint(hi.y);
                }
        }

        uint32_t sA = tile_base + s * STAGE_BYTES;
        uint32_t sB = sA + A_STAGE_BYTES;
        load_frags(0, sA, sB, 0);
        if (i < nc) {
#pragma unroll
            for (int ks = 0; ks < 4; ks++) {
                int cur = ks & 1;
                if (ks < 3) load_frags(cur ^ 1, sA, sB, ks + 1);
#pragma unroll
                for (int mf = 0; mf < 4; mf++)
#pragma unroll
                    for (int nf = 0; nf < 8; nf++)
                        mma_f16(acc[mf][nf], aF[cur][mf], bF[cur][nf]);
            }
        } else {
#pragma unroll
            for (int ks = 0; ks < 4; ks++) {
                int cur = ks & 1;
                if (ks < 3) load_frags(cur ^ 1, sA, sB, ks + 1);
#pragma unroll
                for (int mf = 0; mf < 4; mf++)
#pragma unroll
                    for (int nf = 0; nf < 8; nf++)
                        mma_f32(acc[mf][nf], aF[cur][mf], bF[cur][nf]);
            }
        }
    }

    // epilogue: float2 stores
    int rr = lid >> 2;
    int cc2 = (lid & 3) * 2;
#pragma unroll
    for (int mf = 0; mf < 4; mf++) {
#pragma unroll
        for (int nf = 0; nf < 8; nf++) {
            int m = m0 + wmo + mf * 16 + rr;
            int n = n0 + wno + nf * 8 + cc2;
            float2 v0 = make_float2(__uint_as_float(acc[mf][nf][0]),
                                    __uint_as_float(acc[mf][nf][1]));
            float2 v1 = make_float2(__uint_as_float(acc[mf][nf][2]),
                                    __uint_as_float(acc[mf][nf][3]));
            *(float2*)&g_C[(size_t)m * N9 + n] = v0;
            *(float2*)&g_C[(size_t)(m + 8) * N9 + n] = v1;
        }
    }
}

// ---------------- combine: gate network (float2-vectorized) ----------------
DINLINE float sigf(float v) { return 1.0f / (1.0f + expf(-v)); }

DINLINE float gate_net(float s0, float s1, float s2, float s4, float s5,
                       float s6, float s7, float x3, float m3,
                       float cp, float& nc) {
    float l10 = sigf(s0);
    float l11 = fmaxf(s1, 0.0f);
    float l12 = sigf(s2);
    float l13 = fmaxf(x3 * m3, 0.0f);
    float l14 = tanhf(s4);
    float l15 = sigf(s5);
    float l16 = tanhf(s6);
    float l17 = sigf(s7);
    float l20 = tanhf(l10 * l11);
    float l21 = tanhf(l12 + l13);
    float l22 = tanhf(l14 * l15);
    float l23 = sigf(l16 + l17);
    l20 = tanhf(l20 + cp);
    nc = l20 * l21;
    float l31 = tanhf(l22 + l23);
    return tanhf(nc * l31);
}

__global__ void combine_kernel(const float* __restrict__ c_prev, float* __restrict__ out) {
    size_t idx = (size_t)blockIdx.x * blockDim.x + threadIdx.x;
    if (idx >= (size_t)BQ * (HID / 2)) return;
    size_t b  = idx >> 9;
    int    h2 = (int)(idx & 511);
    const float2* Cr = (const float2*)(g_C + b * N9) + h2;
    float2 s0 = Cr[0],        s1 = Cr[512],      s2 = Cr[1024];
    float2 s4 = Cr[1536],     s5 = Cr[2048],     s6 = Cr[2560];
    float2 s7 = Cr[3072],     x3 = Cr[3584],     m3 = Cr[4096];
    float2 cp = *((const float2*)c_prev + b * 512 + h2);

    float2 nm, nc;
    nm.x = gate_net(s0.x, s1.x, s2.x, s4.x, s5.x, s6.x, s7.x, x3.x, m3.x, cp.x, nc.x);
    nm.y = gate_net(s0.y, s1.y, s2.y, s4.y, s5.y, s6.y, s7.y, x3.y, m3.y, cp.y, nc.y);

    float2* o = (float2*)out;
    o[b * 512 + h2] = nm;                                  // new_m
    o[(size_t)BQ * 512 + b * 512 + h2] = nc;               // new_c
}

// ---------------- launch ----------------
extern "C" void kernel_launch(void* const* d_in, const int* in_sizes, int n_in,
                              void* d_out, int out_size) {
    const float* x      = (const float*)d_in[0];
    const float* m_prev = (const float*)d_in[1];
    const float* c_prev = (const float*)d_in[2];
    const float* w_m    = (const float*)d_in[3];
    const float* w_in   = (const float*)d_in[4];
    float* out = (float*)d_out;

    cudaFuncSetAttribute(gemm_kernel, cudaFuncAttributeMaxDynamicSharedMemorySize, SMEM_DYN);

    {   // pack A (fp16 hi + fp16 residual), 4 elems/thread
        size_t n = (size_t)BQ * 256;
        pack_A<<<(unsigned)((n + 255) / 256), 256>>>(x, m_prev);
    }
    {   // pack B (transpose + fp16 hi/lo)
        dim3 grid(256, 32, 2), blk(32, 8);
        pack_B<<<grid, blk>>>(w_in, w_m);
    }
    {   // the single big two-phase GEMM
        gemm_kernel<<<MT * NT, 128, SMEM_DYN>>>();
    }
    {   // gate network
        size_t n = (size_t)BQ * (HID / 2);
        combine_kernel<<<(unsigned)((n + 255) / 256), 256>>>(c_prev, out);
    }
    (void)in_sizes; (void)n_in; (void)out_size;
}

// round 10
// speedup vs baseline: 2.5516x; 1.0411x over previous
#include <cuda_runtime.h>
#include <cuda_fp16.h>
#include <cstdint>

#define DINLINE __device__ __forceinline__

// ---------------- problem constants ----------------
constexpr int BQ  = 8192;   // batch rows
constexpr int HID = 1024;   // hidden
constexpr int N9  = 9216;   // packed N: 7 sum gates + x3 + m3
constexpr int KC  = 4096;   // correction K (fp16-acc phase): [xl | xh | ml | mh]
constexpr int KM  = 2048;   // main K (f32-acc phase): [xh | mh]

// GEMM tiling: 128x128 CTA tile, 4 warps, 3 stages, 2 CTA/SM, persistent
constexpr int BM = 128, BN = 128, NSTAGE = 3;
constexpr int A_STAGE_BYTES = BM * 128;                      // 16384 (128B/row)
constexpr int STAGE_BYTES   = 2 * A_STAGE_BYTES;             // 32768
constexpr int SMEM_DYN      = NSTAGE * STAGE_BYTES + 1024;

constexpr int MT = BQ / BM;   // 64
constexpr int NT = N9 / BN;   // 72
constexpr int GM = 8;         // m-supertile height
constexpr int NTILES = MT * NT;          // 4608
constexpr int GRID_P = 296;              // 148 SMs x 2 CTAs (all resident)

// ---------------- device scratch (static globals: allowed) ----------------
__device__ __half g_Ac[(size_t)BQ * KC];   // 64 MB  corrections
__device__ __half g_Am[(size_t)BQ * KM];   // 32 MB  main
__device__ __half g_Bc[(size_t)N9 * KC];   // 72 MB
__device__ __half g_Bm[(size_t)N9 * KM];   // 36 MB
__device__ float  g_C [(size_t)BQ * N9];   // 288 MB
__device__ unsigned int g_tile_ctr;        // work-stealing cursor

// ---------------- PTX helpers (sm_80-class only) ----------------
DINLINE uint32_t smem_u32(const void* p) {
    uint32_t a;
    asm("{ .reg .u64 t; cvta.to.shared.u64 t, %1; cvt.u32.u64 %0, t; }"
        : "=r"(a) : "l"(p));
    return a;
}

DINLINE void cp16(uint32_t dst, const void* src) {
    asm volatile("cp.async.cg.shared.global [%0], [%1], 16;" :: "r"(dst), "l"(src));
}
DINLINE void cp_commit() { asm volatile("cp.async.commit_group;" ::: "memory"); }
DINLINE void cp_wait1()  { asm volatile("cp.async.wait_group 1;" ::: "memory"); }

DINLINE void ldsm4(uint32_t& r0, uint32_t& r1, uint32_t& r2, uint32_t& r3,
                   uint32_t addr) {
    asm volatile("ldmatrix.sync.aligned.m8n8.x4.shared.b16 {%0,%1,%2,%3}, [%4];"
                 : "=r"(r0), "=r"(r1), "=r"(r2), "=r"(r3) : "r"(addr));
}

// fp16 x fp16 -> f32 accumulate, acc stored as uint32 bits
DINLINE void mma_f32(uint32_t* c, const uint32_t* a, const uint32_t* b) {
    asm volatile(
        "{\n\t.reg .f32 p0,p1,p2,p3;\n\t"
        "mov.b32 p0,%0; mov.b32 p1,%1; mov.b32 p2,%2; mov.b32 p3,%3;\n\t"
        "mma.sync.aligned.m16n8k16.row.col.f32.f16.f16.f32 "
        "{p0,p1,p2,p3}, {%4,%5,%6,%7}, {%8,%9}, {p0,p1,p2,p3};\n\t"
        "mov.b32 %0,p0; mov.b32 %1,p1; mov.b32 %2,p2; mov.b32 %3,p3;\n\t}"
        : "+r"(c[0]), "+r"(c[1]), "+r"(c[2]), "+r"(c[3])
        : "r"(a[0]), "r"(a[1]), "r"(a[2]), "r"(a[3]), "r"(b[0]), "r"(b[1]));
}

// fp16 x fp16 -> f16 accumulate (2 packed regs)
DINLINE void mma_f16(uint32_t* c, const uint32_t* a, const uint32_t* b) {
    asm volatile(
        "mma.sync.aligned.m16n8k16.row.col.f16.f16.f16.f16 "
        "{%0,%1}, {%2,%3,%4,%5}, {%6,%7}, {%0,%1};"
        : "+r"(c[0]), "+r"(c[1])
        : "r"(a[0]), "r"(a[1]), "r"(a[2]), "r"(a[3]), "r"(b[0]), "r"(b[1]));
}

DINLINE __half2 u32_as_half2(uint32_t u) {
    __half2 h;
    *(uint32_t*)&h = u;
    return h;
}

// ---------------- pack kernels ----------------
// Am row b: [xh | mh]. Ac row b: [xl | xh | ml | mh]  (all fp16)
__global__ void pack_A(const float* __restrict__ x, const float* __restrict__ m) {
    size_t idx = (size_t)blockIdx.x * blockDim.x + threadIdx.x;
    if (idx == 0) g_tile_ctr = GRID_P;      // reset work-stealing cursor
    if (idx >= (size_t)BQ * 256) return;
    size_t b = idx >> 8;
    int k4 = (int)(idx & 255) * 4;

    float xs[4], ms[4];
    *(float4*)xs = *(const float4*)(x + b * 1024 + k4);
    *(float4*)ms = *(const float4*)(m + b * 1024 + k4);

    unsigned short xh[4], xl[4], mh[4], ml[4];
#pragma unroll
    for (int c = 0; c < 4; c++) {
        __half h = __float2half_rn(xs[c]);
        xh[c] = __half_as_ushort(h);
        xl[c] = __half_as_ushort(__float2half_rn(xs[c] - __half2float(h)));
        h = __float2half_rn(ms[c]);
        mh[c] = __half_as_ushort(h);
        ml[c] = __half_as_ushort(__float2half_rn(ms[c] - __half2float(h)));
    }
    *(uint2*)&g_Am[b * KM + k4]        = *(uint2*)xh;
    *(uint2*)&g_Am[b * KM + 1024 + k4] = *(uint2*)mh;
    *(uint2*)&g_Ac[b * KC + k4]        = *(uint2*)xl;
    *(uint2*)&g_Ac[b * KC + 1024 + k4] = *(uint2*)xh;
    *(uint2*)&g_Ac[b * KC + 2048 + k4] = *(uint2*)ml;
    *(uint2*)&g_Ac[b * KC + 3072 + k4] = *(uint2*)mh;
}

// Bm row n: [wih | wmh]. Bc row n: [wih | wil | wmh | wml]
// (corr pairing: xl*wih + xh*wil + ml*wmh + mh*wml)
// block (16,16): tx = k-pair (2 k values -> half2 stores), ty = row step
__global__ void pack_B(const float* __restrict__ wi, const float* __restrict__ wm) {
    __shared__ float t[32][33];
    int ct = blockIdx.x;             // col tile over 8192
    int kt = blockIdx.y;             // k tile over 1024
    int z  = blockIdx.z;             // 0 = w_inputs, 1 = w_m
    const float* w = z ? wm : wi;
    int col0 = ct * 32, k0 = kt * 32;
    int tx = threadIdx.x, ty = threadIdx.y;     // 16 x 16
    for (int r = ty; r < 32; r += 16) {
        t[r][tx]      = w[(size_t)(k0 + r) * 8192 + col0 + tx];
        t[r][tx + 16] = w[(size_t)(k0 + r) * 8192 + col0 + tx + 16];
    }
    __syncthreads();
    for (int r = ty; r < 32; r += 16) {
        int col = col0 + r;
        float v0 = t[2 * tx][r];         // = w[k0+2tx][col]
        float v1 = t[2 * tx + 1][r];     // = w[k0+2tx+1][col]
        __half h0 = __float2half_rn(v0), h1 = __float2half_rn(v1);
        __half l0 = __float2half_rn(v0 - __half2float(h0));
        __half l1 = __float2half_rn(v1 - __half2float(h1));
        __half2 hi2 = __halves2half2(h0, h1);
        __half2 lo2 = __halves2half2(l0, l1);
        int g = col >> 10, h = col & 1023;
        size_t n;
        if (g == 3) n = z ? (size_t)(8192 + h) : (size_t)(7168 + h);
        else        n = (size_t)((g < 3 ? g : g - 1) * 1024 + h);
        int kk = k0 + 2 * tx;
        *(__half2*)&g_Bm[n * KM + z * 1024 + kk]        = hi2;
        *(__half2*)&g_Bc[n * KC + z * 2048 + kk]        = hi2;
        *(__half2*)&g_Bc[n * KC + z * 2048 + 1024 + kk] = lo2;
    }
}

// ---------------- GEMM: persistent, fp16-acc corr phase + f32-acc main ----
__global__ __launch_bounds__(128, 2)
void gemm_kernel() {
    extern __shared__ char dsmem[];
    __shared__ unsigned int s_next;
    char* tilep = (char*)(((uintptr_t)dsmem + 1023) & ~(uintptr_t)1023);
    uint32_t tile_base = smem_u32(tilep);

    int tid = threadIdx.x;
    int wid = tid >> 5;
    int lid = tid & 31;
    int wmo = (wid & 1) * 64;    // warp m-offset (2 warps in m)
    int wno = (wid >> 1) * 64;   // warp n-offset (2 warps in n)

    int rowA = wmo + (lid & 15);                      // + mf*16
    int kAby = (lid >> 4) * 16;                       // + ks*32 bytes
    int rowB = wno + (lid & 7) + (lid >> 4) * 8;      // + nf2*16
    int kBby = ((lid >> 3) & 1) * 16;                 // + ks*32 bytes

    unsigned int tile = blockIdx.x;

    while (tile < NTILES) {
        // supertile mapping (bands of GM m-tiles sweep all n)
        int mt = (tile / (GM * NT)) * GM + (tile % GM);
        int nt = (tile / GM) % NT;
        int m0 = mt * BM;
        int n0 = nt * BN;

        // region: byte offsets within packed rows + stage counts (128B each)
        int cbeg, nc, mbeg, nm;
        if (n0 >= 8192)      { cbeg = 4096; nc = 32; mbeg = 2048; nm = 16; } // m3
        else if (n0 >= 7168) { cbeg = 0;    nc = 32; mbeg = 0;    nm = 16; } // x3
        else                 { cbeg = 0;    nc = 64; mbeg = 0;    nm = 32; } // sums
        int NS = nc + nm;

        const char* pAc = (const char*)g_Ac + (size_t)m0 * (KC * 2) + cbeg;
        const char* pAm = (const char*)g_Am + (size_t)m0 * (KM * 2) + mbeg;
        const char* pBc = (const char*)g_Bc + (size_t)n0 * (KC * 2) + cbeg;
        const char* pBm = (const char*)g_Bm + (size_t)n0 * (KM * 2) + mbeg;

        auto fill_stage = [&](int s, int i) {
            bool corr = (i < nc);
            const char* gA = corr ? pAc + i * 128 : pAm + (i - nc) * 128;
            const char* gB = corr ? pBc + i * 128 : pBm + (i - nc) * 128;
            size_t stride = corr ? (size_t)(KC * 2) : (size_t)(KM * 2);
            uint32_t baseA = tile_base + s * STAGE_BYTES;
            uint32_t baseB = baseA + A_STAGE_BYTES;
#pragma unroll
            for (int j = 0; j < 16; j++) {
                int ch = tid + (j << 7);           // 0..2047
                int rr = (ch >> 3) & 127;
                int cc = ch & 7;
                uint32_t off = (uint32_t)((rr << 7) + (cc << 4));
                uint32_t sw  = off ^ ((off >> 3) & 0x70);
                const char* src = ((ch < 1024) ? gA : gB) + (size_t)rr * stride + (cc << 4);
                cp16(((ch < 1024) ? baseA : baseB) + sw, src);
            }
        };

        // accumulator union: f16 pair in [0..1] during corr phase,
        // f32 bits in [0..3] after the in-place expansion
        uint32_t acc[4][8][4];
#pragma unroll
        for (int mf = 0; mf < 4; mf++)
#pragma unroll
            for (int nf = 0; nf < 8; nf++) {
                acc[mf][nf][0] = 0u; acc[mf][nf][1] = 0u;
                acc[mf][nf][2] = 0u; acc[mf][nf][3] = 0u;
            }

        fill_stage(0, 0); cp_commit();
        fill_stage(1, 1); cp_commit();

        uint32_t aF[2][4][4];
        uint32_t bF[2][8][2];

        auto load_frags = [&](int buf, uint32_t sA, uint32_t sB, int ks) {
#pragma unroll
            for (int mf = 0; mf < 4; mf++) {
                uint32_t off = (uint32_t)((rowA + mf * 16) << 7);
                uint32_t addr = sA + off + (((uint32_t)(kAby + ks * 32)) ^ ((off >> 3) & 0x70));
                ldsm4(aF[buf][mf][0], aF[buf][mf][1], aF[buf][mf][2], aF[buf][mf][3], addr);
            }
#pragma unroll
            for (int nf2 = 0; nf2 < 4; nf2++) {
                uint32_t off = (uint32_t)((rowB + nf2 * 16) << 7);
                uint32_t addr = sB + off + (((uint32_t)(kBby + ks * 32)) ^ ((off >> 3) & 0x70));
                uint32_t r0, r1, r2, r3;
                ldsm4(r0, r1, r2, r3, addr);
                bF[buf][nf2 * 2][0] = r0;      bF[buf][nf2 * 2][1] = r1;
                bF[buf][nf2 * 2 + 1][0] = r2;  bF[buf][nf2 * 2 + 1][1] = r3;
            }
        };

        for (int i = 0; i < NS; i++) {
            int s = i - (i / NSTAGE) * NSTAGE;            // i % 3
            // SAFE order: wait fill(i); barrier (readers of stage (i+2)%3
            // done); first frag loads; only then refill that stage.
            cp_wait1();
            __syncthreads();

            if (i == nc) {   // phase boundary: expand fp16 acc -> f32 bits
#pragma unroll
                for (int mf = 0; mf < 4; mf++)
#pragma unroll
                    for (int nf = 0; nf < 8; nf++) {
                        float2 lo = __half22float2(u32_as_half2(acc[mf][nf][0]));
                        float2 hi = __half22float2(u32_as_half2(acc[mf][nf][1]));
                        acc[mf][nf][0] = __float_as_uint(lo.x);
                        acc[mf][nf][1] = __float_as_uint(lo.y);
                        acc[mf][nf][2] = __float_as_uint(hi.x);
                        acc[mf][nf][3] = __float_as_uint(hi.y);
                    }
            }

            uint32_t sA = tile_base + s * STAGE_BYTES;
            uint32_t sB = sA + A_STAGE_BYTES;
            load_frags(0, sA, sB, 0);                     // start compute feed
            if (i + 2 < NS) fill_stage((s + 2 >= NSTAGE) ? s + 2 - NSTAGE : s + 2, i + 2);
            cp_commit();

            if (i < nc) {
#pragma unroll
                for (int ks = 0; ks < 4; ks++) {
                    int cur = ks & 1;
                    if (ks < 3) load_frags(cur ^ 1, sA, sB, ks + 1);
#pragma unroll
                    for (int mf = 0; mf < 4; mf++)
#pragma unroll
                        for (int nf = 0; nf < 8; nf++)
                            mma_f16(acc[mf][nf], aF[cur][mf], bF[cur][nf]);
                }
            } else {
#pragma unroll
                for (int ks = 0; ks < 4; ks++) {
                    int cur = ks & 1;
                    if (ks < 3) load_frags(cur ^ 1, sA, sB, ks + 1);
#pragma unroll
                    for (int mf = 0; mf < 4; mf++)
#pragma unroll
                        for (int nf = 0; nf < 8; nf++)
                            mma_f32(acc[mf][nf], aF[cur][mf], bF[cur][nf]);
                }
            }
        }

        // epilogue: float2 stores
        int rr = lid >> 2;
        int cc2 = (lid & 3) * 2;
#pragma unroll
        for (int mf = 0; mf < 4; mf++) {
#pragma unroll
            for (int nf = 0; nf < 8; nf++) {
                int m = m0 + wmo + mf * 16 + rr;
                int n = n0 + wno + nf * 8 + cc2;
                float2 v0 = make_float2(__uint_as_float(acc[mf][nf][0]),
                                        __uint_as_float(acc[mf][nf][1]));
                float2 v1 = make_float2(__uint_as_float(acc[mf][nf][2]),
                                        __uint_as_float(acc[mf][nf][3]));
                *(float2*)&g_C[(size_t)m * N9 + n] = v0;
                *(float2*)&g_C[(size_t)(m + 8) * N9 + n] = v1;
            }
        }

        // steal next tile
        if (tid == 0) s_next = atomicAdd(&g_tile_ctr, 1u);
        __syncthreads();                 // also guards smem reuse next tile
        tile = s_next;
    }
}

// ---------------- combine: gate network (float4 + int32 indexing) ---------
DINLINE float sigf(float v) { return 1.0f / (1.0f + expf(-v)); }

DINLINE float gate_net(float s0, float s1, float s2, float s4, float s5,
                       float s6, float s7, float x3, float m3,
                       float cp, float& nc) {
    float l10 = sigf(s0);
    float l11 = fmaxf(s1, 0.0f);
    float l12 = sigf(s2);
    float l13 = fmaxf(x3 * m3, 0.0f);
    float l14 = tanhf(s4);
    float l15 = sigf(s5);
    float l16 = tanhf(s6);
    float l17 = sigf(s7);
    float l20 = tanhf(l10 * l11);
    float l21 = tanhf(l12 + l13);
    float l22 = tanhf(l14 * l15);
    float l23 = sigf(l16 + l17);
    l20 = tanhf(l20 + cp);
    nc = l20 * l21;
    float l31 = tanhf(l22 + l23);
    return tanhf(nc * l31);
}

__global__ void combine_kernel(const float* __restrict__ c_prev, float* __restrict__ out) {
    int idx = blockIdx.x * blockDim.x + threadIdx.x;      // < 8192*256
    if (idx >= BQ * 256) return;
    int b  = idx >> 8;
    int h4 = idx & 255;
    const float4* Cr = (const float4*)(g_C + (size_t)b * N9) + h4;
    float4 s0 = Cr[0],        s1 = Cr[256],     s2 = Cr[512];
    float4 s4 = Cr[768],      s5 = Cr[1024],    s6 = Cr[1280];
    float4 s7 = Cr[1536],     x3 = Cr[1792],    m3 = Cr[2048];
    float4 cp = ((const float4*)c_prev)[b * 256 + h4];

    float4 nm, nc;
    nm.x = gate_net(s0.x, s1.x, s2.x, s4.x, s5.x, s6.x, s7.x, x3.x, m3.x, cp.x, nc.x);
    nm.y = gate_net(s0.y, s1.y, s2.y, s4.y, s5.y, s6.y, s7.y, x3.y, m3.y, cp.y, nc.y);
    nm.z = gate_net(s0.z, s1.z, s2.z, s4.z, s5.z, s6.z, s7.z, x3.z, m3.z, cp.z, nc.z);
    nm.w = gate_net(s0.w, s1.w, s2.w, s4.w, s5.w, s6.w, s7.w, x3.w, m3.w, cp.w, nc.w);

    float4* o = (float4*)out;
    o[b * 256 + h4] = nm;                            // new_m
    o[BQ * 256 + b * 256 + h4] = nc;                 // new_c
}

// ---------------- launch ----------------
extern "C" void kernel_launch(void* const* d_in, const int* in_sizes, int n_in,
                              void* d_out, int out_size) {
    const float* x      = (const float*)d_in[0];
    const float* m_prev = (const float*)d_in[1];
    const float* c_prev = (const float*)d_in[2];
    const float* w_m    = (const float*)d_in[3];
    const float* w_in   = (const float*)d_in[4];
    float* out = (float*)d_out;

    cudaFuncSetAttribute(gemm_kernel, cudaFuncAttributeMaxDynamicSharedMemorySize, SMEM_DYN);

    {   // pack A (fp16 hi + fp16 residual) + cursor reset
        size_t n = (size_t)BQ * 256;
        pack_A<<<(unsigned)((n + 255) / 256), 256>>>(x, m_prev);
    }
    {   // pack B (transpose + fp16 hi/lo, half2 stores)
        dim3 grid(256, 32, 2), blk(16, 16);
        pack_B<<<grid, blk>>>(w_in, w_m);
    }
    {   // persistent two-phase GEMM (work-stealing)
        gemm_kernel<<<GRID_P, 128, SMEM_DYN>>>();
    }
    {   // gate network
        int n = BQ * 256;
        combine_kernel<<<(n + 255) / 256, 256>>>(c_prev, out);
    }
    (void)in_sizes; (void)n_in; (void)out_size;
}